// round 3
// baseline (speedup 1.0000x reference)
#include <cuda_runtime.h>

#define B_  4
#define K_  16
#define H_  480
#define W_  640
#define HW_ (H_*W_)
#define P_  200000

// Early-termination threshold on transmittance. Remaining contribution after
// T < EPS is bounded by EPS * |feat| (~5e-5 abs) vs ref RMS ~0.5 -> ~1e-4 rel.
#define EPS_T 1e-4f

// Pre-packed point-cloud features: one aligned 16B row per point -> exactly one
// 32B L2 sector per gather (the minimum possible).
__device__ float4 g_tab[P_];

__global__ void prep_kernel(const float* __restrict__ pt) {
    int i = blockIdx.x * blockDim.x + threadIdx.x;
    if (i < P_) {
        g_tab[i] = make_float4(pt[i], pt[P_ + i], pt[2 * P_ + i], 0.f);
    }
}

__global__ void __launch_bounds__(256) composite_kernel(
    const int*   __restrict__ frag,   // int32 (JAX demotes int64 without x64 mode)
    const float* __restrict__ alpha,
    const float* __restrict__ im,
    float*       __restrict__ out)
{
    int p = blockIdx.x * blockDim.x + threadIdx.x;  // pixel index within a batch image
    int b = blockIdx.y;
    size_t base = (size_t)b * K_ * HW_ + p;

    // Layer 0 decides background. Don't early-return: keep the warp converged
    // for the __any_sync ballot; bg lanes just carry T=0 through the loop.
    int  f0 = frag[base];
    bool bg = (f0 < 0);
    float T = bg ? 0.f : 1.f;
    float c0 = 0.f, c1 = 0.f, c2 = 0.f;

    #pragma unroll
    for (int k = 0; k < K_; k++) {
        // Whole-warp early exit: skips the streaming frag/alpha loads of the
        // remaining layers entirely (each 128B line belongs to one warp).
        if (!__any_sync(0xffffffffu, T > EPS_T)) break;

        size_t off = base + (size_t)k * HW_;
        int   f  = (k == 0) ? f0 : frag[off];
        float al = alpha[off];
        // Per-lane: invalid fragment => weight exactly 0; T < EPS => negligible.
        if (f >= 0 && T > EPS_T) {
            float w = al * T;
            float4 ft = __ldg(&g_tab[f]);
            c0 = fmaf(w, ft.x, c0);
            c1 = fmaf(w, ft.y, c1);
            c2 = fmaf(w, ft.z, c2);
            T *= (1.f - al);          // transmittance decays only through valid fragments
        }
    }

    size_t ob = (size_t)b * 3 * HW_ + p;
    out[ob          ] = bg ? im[p          ] : c0;
    out[ob +     HW_] = bg ? im[p +     HW_] : c1;
    out[ob + 2 * HW_] = bg ? im[p + 2 * HW_] : c2;
}

extern "C" void kernel_launch(void* const* d_in, const int* in_sizes, int n_in,
                              void* d_out, int out_size) {
    const int*   frag  = (const int*)  d_in[0];  // int32 fragments
    const float* alpha = (const float*)d_in[1];
    const float* pt    = (const float*)d_in[2];
    const float* im    = (const float*)d_in[3];
    float*       out   = (float*)      d_out;

    prep_kernel<<<(P_ + 255) / 256, 256>>>(pt);

    dim3 grid(HW_ / 256, B_);   // 307200 % 256 == 0
    composite_kernel<<<grid, 256>>>(frag, alpha, im, out);
}

// round 4
// speedup vs baseline: 1.4337x; 1.4337x over previous
#include <cuda_runtime.h>

#define B_  4
#define K_  16
#define H_  480
#define W_  640
#define HW_ (H_*W_)
#define P_  200000

// Truncation threshold on exclusive transmittance (same semantics as R3's
// measured rel_err = 4.1e-5).
#define EPS_T 1e-4f

// Pre-packed point-cloud features: one aligned 16B row per point -> exactly one
// 32B L2 sector per gather (the minimum possible).
__device__ float4 g_tab[P_];

__global__ void prep_kernel(const float* __restrict__ pt) {
    int i = blockIdx.x * blockDim.x + threadIdx.x;
    if (i < P_) {
        g_tab[i] = make_float4(pt[i], pt[P_ + i], pt[2 * P_ + i], 0.f);
    }
}

__global__ void __launch_bounds__(256) composite_kernel(
    const int*   __restrict__ frag,   // int32 (JAX demotes int64 without x64 mode)
    const float* __restrict__ alpha,
    const float* __restrict__ im,
    float*       __restrict__ out)
{
    int p = blockIdx.x * blockDim.x + threadIdx.x;  // pixel within a batch image
    int b = blockIdx.y;
    size_t base = (size_t)b * K_ * HW_ + p;

    float T  = 1.f;
    float c0 = 0.f, c1 = 0.f, c2 = 0.f;
    bool  bg = false;

    #pragma unroll
    for (int half = 0; half < 2; half++) {
        // Phase 1: batch-load 8 frags + 8 alphas (16 independent LDGs -> full MLP).
        int   f[8];
        float w[8];
        #pragma unroll
        for (int j = 0; j < 8; j++) {
            size_t off = base + (size_t)(half * 8 + j) * HW_;
            f[j] = frag[off];
            w[j] = alpha[off];
        }
        if (half == 0) bg = (f[0] < 0);

        // Phase 2: weight chain in pure FMA; data-predicated truncation.
        #pragma unroll
        for (int j = 0; j < 8; j++) {
            bool  v  = (f[j] >= 0);
            float av = v ? w[j] : 0.f;
            w[j] = (v && T > EPS_T) ? av * T : 0.f;   // exclusive-transmittance weight
            T *= (1.f - av);                          // decays only through valid frags
        }

        // Phase 3: predicated independent gathers (skip zero-weight layers).
        #pragma unroll
        for (int j = 0; j < 8; j++) {
            if (w[j] != 0.f) {
                float4 ft = __ldg(&g_tab[f[j]]);
                c0 = fmaf(w[j], ft.x, c0);
                c1 = fmaf(w[j], ft.y, c1);
                c2 = fmaf(w[j], ft.z, c2);
            }
        }

        // Phase 4: single mid-point ballot — if the whole warp is saturated
        // (or background), skip the second half's 16 streaming loads.
        if (half == 0 && !__any_sync(0xffffffffu, T > EPS_T)) break;
    }

    size_t ob = (size_t)b * 3 * HW_ + p;
    out[ob          ] = bg ? im[p          ] : c0;
    out[ob +     HW_] = bg ? im[p +     HW_] : c1;
    out[ob + 2 * HW_] = bg ? im[p + 2 * HW_] : c2;
}

extern "C" void kernel_launch(void* const* d_in, const int* in_sizes, int n_in,
                              void* d_out, int out_size) {
    const int*   frag  = (const int*)  d_in[0];  // int32 fragments
    const float* alpha = (const float*)d_in[1];
    const float* pt    = (const float*)d_in[2];
    const float* im    = (const float*)d_in[3];
    float*       out   = (float*)      d_out;

    prep_kernel<<<(P_ + 255) / 256, 256>>>(pt);

    dim3 grid(HW_ / 256, B_);   // 307200 % 256 == 0
    composite_kernel<<<grid, 256>>>(frag, alpha, im, out);
}